// round 1
// baseline (speedup 1.0000x reference)
#include <cuda_runtime.h>
#include <math.h>

#define BB 4096
#define DD 2048
#define KK 8
#define PCOLS 25   // 3K+1

__device__ __forceinline__ float dev_nan_guard(float v) { return v; }

constexpr float RMIN = -5.0f;
constexpr float RMAX = 5.0f;
constexpr float MIN_BIN = 1e-3f;
constexpr float MIN_SLOPE = 1e-3f;
constexpr float MAX_SLOPE = 10.0f;

// Precomputed per-d tables, SoA layout [field][D]:
//  0..6   : xk[1..7]        (interior knots, for register-resident binary search)
//  7..14  : yk[0..7]        (y_k per bin)
// 15..22  : h[0..7]         (height per bin)
// 23..30  : rw[0..7]        (1/width per bin)
// 31..38  : s[0..7]         (height/width per bin)
// 39..47  : slopes[0..8]
// 48      : log(slopes[0])
// 49      : log(slopes[8])
#define NFIELD 50
__device__ float g_par[NFIELD * DD];

__global__ void norm_kernel(const float* __restrict__ params) {
    int d = blockIdx.x * blockDim.x + threadIdx.x;
    if (d >= DD) return;
    const float* p = params + (size_t)d * PCOLS;

    float ws[KK], hs[KK], sl[KK + 1];
    float sw = 0.f, sh = 0.f;
#pragma unroll
    for (int j = 0; j < KK; j++) { float v = 1.f / (1.f + expf(-p[j]));       ws[j] = v; sw += v; }
#pragma unroll
    for (int j = 0; j < KK; j++) { float v = 1.f / (1.f + expf(-p[KK + j])); hs[j] = v; sh += v; }
#pragma unroll
    for (int j = 0; j < KK + 1; j++) {
        float v = 1.f / (1.f + expf(-p[2 * KK + j]));
        sl[j] = MIN_SLOPE + v * (MAX_SLOPE - MIN_SLOPE);
    }

    float rem = (RMAX - RMIN) - KK * MIN_BIN;
    float fw = rem / sw;
    float fh = rem / sh;

    float xk[KK + 1], yk[KK + 1], wd[KK];
    xk[0] = RMIN; yk[0] = RMIN;
#pragma unroll
    for (int j = 0; j < KK; j++) {
        wd[j] = MIN_BIN + ws[j] * fw;
        float ht = MIN_BIN + hs[j] * fh;
        xk[j + 1] = xk[j] + wd[j];
        yk[j + 1] = yk[j] + ht;
    }

#pragma unroll
    for (int j = 1; j <= 7; j++) g_par[(j - 1) * DD + d] = xk[j];
#pragma unroll
    for (int j = 0; j < KK; j++) {
        float ht = yk[j + 1] - yk[j];
        float rw = 1.f / wd[j];
        g_par[(7 + j)  * DD + d] = yk[j];
        g_par[(15 + j) * DD + d] = ht;
        g_par[(23 + j) * DD + d] = rw;
        g_par[(31 + j) * DD + d] = ht * rw;
    }
#pragma unroll
    for (int j = 0; j < KK + 1; j++) g_par[(39 + j) * DD + d] = sl[j];
    g_par[48 * DD + d] = logf(sl[0]);
    g_par[49 * DD + d] = logf(sl[KK]);
}

#define DT 256   // columns per CTA (== blockDim.x)
#define BT 64    // rows per CTA

// smem fields (per 256 columns):
//  0..7  yk, 8..15 h, 16..23 rw, 24..31 s, 32..40 slopes
#define SMF 41

__global__ void __launch_bounds__(DT) eval_kernel(const float* __restrict__ x,
                                                  float* __restrict__ y,
                                                  float* __restrict__ ld_out) {
    __shared__ float sm[SMF * DT];

    const int tid = threadIdx.x;
    const int d = blockIdx.x * DT + tid;
    const int lane = tid & 31;

    // stage tables into smem (coalesced: consecutive d per field)
#pragma unroll
    for (int f = 0; f < SMF; f++) sm[f * DT + tid] = g_par[(7 + f) * DD + d];

    // per-thread register-resident interior knots + tail constants (d fixed)
    const float v1 = g_par[0 * DD + d];
    const float v2 = g_par[1 * DD + d];
    const float v3 = g_par[2 * DD + d];
    const float v4 = g_par[3 * DD + d];
    const float v5 = g_par[4 * DD + d];
    const float v6 = g_par[5 * DD + d];
    const float v7 = g_par[6 * DD + d];
    const float s0  = g_par[39 * DD + d];
    const float sK  = g_par[47 * DD + d];
    const float ls0 = g_par[48 * DD + d];
    const float lsK = g_par[49 * DD + d];

    __syncthreads();

    const int b0 = blockIdx.y * BT;

#pragma unroll 4
    for (int r = 0; r < BT; r++) {
        const int b = b0 + r;
        const float xv = __ldg(&x[(size_t)b * DD + d]);

        // 3-level binary search over interior knots (registers only)
        int bin = 0;
        float xk_lo = RMIN;
        if (xv >= v4) { bin = 4; xk_lo = v4; }
        const float c2 = (bin & 4) ? v6 : v2;
        if (xv >= c2) { bin += 2; xk_lo = c2; }
        const float c1 = (bin & 4) ? ((bin & 2) ? v7 : v5)
                                   : ((bin & 2) ? v3 : v1);
        if (xv >= c1) { bin += 1; xk_lo = c1; }

        // 6 conflict-free gathers (bank = tid%32 independent of bin)
        const float y_k = sm[(0  + bin) * DT + tid];
        const float h   = sm[(8  + bin) * DT + tid];
        const float rw  = sm[(16 + bin) * DT + tid];
        const float s   = sm[(24 + bin) * DT + tid];
        const float dk  = sm[(32 + bin) * DT + tid];
        const float dk1 = sm[(33 + bin) * DT + tid];

        const float xi  = (xv - xk_lo) * rw;
        const float xi1 = 1.f - xi;
        const float xx  = xi * xi;
        const float xx1 = xi * xi1;

        const float num  = s * xx + dk * xx1;
        const float den  = s + (dk1 + dk - 2.f * s) * xx1;
        const float rden = __fdividef(1.f, den);

        const float y_spline = fmaf(h * num, rden, y_k);
        const float dnum = s * s * (dk1 * xx + 2.f * s * xx1 + dk * xi1 * xi1);
        float ldv = __logf(dnum * rden * rden);

        const bool below = (xv <= RMIN);
        const bool above = (xv >= RMAX);
        float yv = y_spline;
        if (above) { yv = fmaf(xv - RMAX, sK, RMAX); ldv = lsK; }
        if (below) { yv = fmaf(xv - RMIN, s0, RMIN); ldv = ls0; }

        y[(size_t)b * DD + d] = yv;

        // warp reduce logdet, one RED per warp per row
        ldv += __shfl_xor_sync(0xffffffffu, ldv, 16);
        ldv += __shfl_xor_sync(0xffffffffu, ldv, 8);
        ldv += __shfl_xor_sync(0xffffffffu, ldv, 4);
        ldv += __shfl_xor_sync(0xffffffffu, ldv, 2);
        ldv += __shfl_xor_sync(0xffffffffu, ldv, 1);
        if (lane == 0) atomicAdd(&ld_out[b], ldv);
    }
}

extern "C" void kernel_launch(void* const* d_in, const int* in_sizes, int n_in,
                              void* d_out, int out_size) {
    // inputs: x [B,D] fp32, params [D, 25] fp32 (order-robust via sizes)
    const float* x;
    const float* params;
    if (in_sizes[0] == BB * DD) { x = (const float*)d_in[0]; params = (const float*)d_in[1]; }
    else                        { x = (const float*)d_in[1]; params = (const float*)d_in[0]; }

    float* y_out  = (float*)d_out;              // [B, D]
    float* ld_out = y_out + (size_t)BB * DD;    // [B]

    norm_kernel<<<(DD + 255) / 256, 256>>>(params);
    cudaMemsetAsync(ld_out, 0, BB * sizeof(float), 0);
    dim3 grid(DD / DT, BB / BT);
    eval_kernel<<<grid, DT>>>(x, y_out, ld_out);
}

// round 3
// speedup vs baseline: 1.2054x; 1.2054x over previous
#include <cuda_runtime.h>
#include <math.h>

#define BB 4096
#define DD 2048
#define KK 8
#define PCOLS 25   // 3K+1

constexpr float RMIN = -5.0f;
constexpr float RMAX = 5.0f;
constexpr float MIN_BIN = 1e-3f;
constexpr float MIN_SLOPE = 1e-3f;
constexpr float MAX_SLOPE = 10.0f;

// Packed main table: [9][DD] of float4 {y_k, h, 1/w, slope_j}; row 8 = {0,0,0,slope_8}.
// dk1 for bin j is row j+1's .w — one immediate-offset LDS.32 away from the float4.
__device__ float4 g_main[9 * DD];
// Interior knots x_k[1..7], SoA [7][DD], kept in registers per thread in eval.
__device__ float  g_knots[7 * DD];

__global__ void norm_kernel(const float* __restrict__ params, float* __restrict__ ld_out) {
    const int d = blockIdx.x * blockDim.x + threadIdx.x;
    if (d < DD) {
        const float* p = params + (size_t)d * PCOLS;

        float ws[KK], hs[KK], sl[KK + 1];
        float sw = 0.f, sh = 0.f;
#pragma unroll
        for (int j = 0; j < KK; j++) { float v = 1.f / (1.f + expf(-p[j]));      ws[j] = v; sw += v; }
#pragma unroll
        for (int j = 0; j < KK; j++) { float v = 1.f / (1.f + expf(-p[KK + j])); hs[j] = v; sh += v; }
#pragma unroll
        for (int j = 0; j < KK + 1; j++) {
            float v = 1.f / (1.f + expf(-p[2 * KK + j]));
            sl[j] = MIN_SLOPE + v * (MAX_SLOPE - MIN_SLOPE);
        }

        const float rem = (RMAX - RMIN) - KK * MIN_BIN;
        const float fw = rem / sw;
        const float fh = rem / sh;

        float xk = RMIN, yk = RMIN;
#pragma unroll
        for (int j = 0; j < KK; j++) {
            const float wd = MIN_BIN + ws[j] * fw;
            const float ht = MIN_BIN + hs[j] * fh;
            float4 v;
            v.x = yk;
            v.y = ht;
            v.z = 1.f / wd;
            v.w = sl[j];
            g_main[j * DD + d] = v;
            xk += wd;
            yk += ht;
            if (j < 7) g_knots[j * DD + d] = xk;
        }
        g_main[8 * DD + d] = make_float4(0.f, 0.f, 0.f, sl[KK]);
    }
    // zero logdet accumulator (4096 floats, 2048 threads -> 2 each)
    const int t = blockIdx.x * blockDim.x + threadIdx.x;
    if (t < BB / 2) { ld_out[t] = 0.f; ld_out[t + BB / 2] = 0.f; }
}

#define DT 256   // columns per CTA (== blockDim.x)
#define BT 32    // rows per CTA

__global__ void __launch_bounds__(DT) eval_kernel(const float* __restrict__ x,
                                                  float* __restrict__ y,
                                                  float* __restrict__ ld_out) {
    __shared__ float4 sm4[9 * DT];   // 36 KB

    const int tid = threadIdx.x;
    const int lane = tid & 31;
    const int d = blockIdx.x * DT + tid;

    // stage packed table into smem; grab boundary slopes for free
    float s0 = 0.f, sK = 0.f;
#pragma unroll
    for (int j = 0; j < 9; j++) {
        const float4 v = g_main[j * DD + d];
        sm4[j * DT + tid] = v;
        if (j == 0) s0 = v.w;
        if (j == 8) sK = v.w;
    }
    const float v1 = g_knots[0 * DD + d];
    const float v2 = g_knots[1 * DD + d];
    const float v3 = g_knots[2 * DD + d];
    const float v4 = g_knots[3 * DD + d];
    const float v5 = g_knots[4 * DD + d];
    const float v6 = g_knots[5 * DD + d];
    const float v7 = g_knots[6 * DD + d];
    const float ls0 = __logf(s0);
    const float lsK = __logf(sK);
    __syncthreads();

    const int b0 = blockIdx.y * BT;
    const float* xp = x + (size_t)b0 * DD + d;
    float*       yp = y + (size_t)b0 * DD + d;

    // lane-dependent constants for the transpose reduction
    const bool k4 = (lane & 16) != 0;
    const bool k2 = (lane & 8)  != 0;
    const bool k1 = (lane & 4)  != 0;
    const int  red_row = ((lane >> 4) & 1) * 4 + ((lane >> 3) & 1) * 2 + ((lane >> 2) & 1);

#pragma unroll
    for (int chunk = 0; chunk < BT / 8; chunk++) {
        float v[8];
#pragma unroll
        for (int r = 0; r < 8; r++) {
            const float xv = __ldg(xp);
            xp += DD;

            // 3-level binary search in registers, carrying the lower knot
            int bin = 0;
            float lo = RMIN;
            if (xv >= v4) { bin = 4; lo = v4; }
            const float c2 = (bin & 4) ? v6 : v2;
            if (xv >= c2) { bin += 2; lo = c2; }
            const float c1 = (bin & 4) ? ((bin & 2) ? v7 : v5)
                                       : ((bin & 2) ? v3 : v1);
            if (xv >= c1) { bin += 1; lo = c1; }

            // one LDS.128 + one immediate-offset LDS.32 (conflict-free)
            const float4* p = &sm4[bin * DT + tid];
            const float4 t = *p;          // {y_k, h, rw, dk}
            const float dk1 = p[DT].w;    // next bin's slope

            const float s   = t.y * t.z;  // h / w
            const float xi  = (xv - lo) * t.z;
            const float xi1 = 1.f - xi;
            const float xx  = xi * xi;
            const float xx1 = xi * xi1;
            const float x11 = xi1 * xi1;

            const float num  = s * xx + t.w * xx1;
            const float den  = fmaf(dk1 + t.w - 2.f * s, xx1, s);
            const float rden = __fdividef(1.f, den);

            float yv = fmaf(t.y * num, rden, t.x);
            const float dnum = s * s * fmaf(dk1, xx, fmaf(2.f * s, xx1, t.w * x11));
            float ldv = __logf(dnum * rden * rden);

            const bool below = (xv <= RMIN);
            const bool above = (xv >= RMAX);
            if (above) { yv = fmaf(xv - RMAX, sK, RMAX); ldv = lsK; }
            if (below) { yv = fmaf(xv - RMIN, s0, RMIN); ldv = ls0; }

            *yp = yv;
            yp += DD;
            v[r] = ldv;
        }

        // Transpose-reduce 8 row-sums across the warp: 9 shuffles total.
        // Stage 1 (xor 16): 8 -> 4 values; lanes with bit4 keep rows 4..7.
        float w4[4];
#pragma unroll
        for (int i = 0; i < 4; i++) {
            const float keep = k4 ? v[i + 4] : v[i];
            const float send = k4 ? v[i] : v[i + 4];
            w4[i] = keep + __shfl_xor_sync(0xffffffffu, send, 16);
        }
        // Stage 2 (xor 8): 4 -> 2
        float w2[2];
#pragma unroll
        for (int i = 0; i < 2; i++) {
            const float keep = k2 ? w4[i + 2] : w4[i];
            const float send = k2 ? w4[i] : w4[i + 2];
            w2[i] = keep + __shfl_xor_sync(0xffffffffu, send, 8);
        }
        // Stage 3 (xor 4): 2 -> 1
        float z = (k1 ? w2[1] : w2[0]) + __shfl_xor_sync(0xffffffffu, k1 ? w2[0] : w2[1], 4);
        // Stages 4-5: sum the 4 lanes (bits 0-1) holding the same row
        z += __shfl_xor_sync(0xffffffffu, z, 2);
        z += __shfl_xor_sync(0xffffffffu, z, 1);

        if ((lane & 3) == 0) atomicAdd(&ld_out[b0 + chunk * 8 + red_row], z);
    }
}

extern "C" void kernel_launch(void* const* d_in, const int* in_sizes, int n_in,
                              void* d_out, int out_size) {
    const float* x;
    const float* params;
    if (in_sizes[0] == BB * DD) { x = (const float*)d_in[0]; params = (const float*)d_in[1]; }
    else                        { x = (const float*)d_in[1]; params = (const float*)d_in[0]; }

    float* y_out  = (float*)d_out;              // [B, D]
    float* ld_out = y_out + (size_t)BB * DD;    // [B]

    norm_kernel<<<DD / 256, 256>>>(params, ld_out);
    dim3 grid(DD / DT, BB / BT);
    eval_kernel<<<grid, DT>>>(x, y_out, ld_out);
}

// round 4
// speedup vs baseline: 1.2541x; 1.0404x over previous
#include <cuda_runtime.h>
#include <math.h>

#define BB 4096
#define DD 2048
#define KK 8
#define PCOLS 25   // 3K+1

constexpr float RMIN = -5.0f;
constexpr float RMAX = 5.0f;
constexpr float MIN_BIN = 1e-3f;
constexpr float MIN_SLOPE = 1e-3f;
constexpr float MAX_SLOPE = 10.0f;

// Packed main table: [9][DD] of float4 {y_k, h, 1/w, slope_j}; row 8 = {0,0,0,slope_8}.
__device__ float4 g_main[9 * DD];
// Interior knots x_k[1..7], SoA [7][DD].
__device__ float  g_knots[7 * DD];

__global__ void norm_kernel(const float* __restrict__ params, float* __restrict__ ld_out) {
    const int d = blockIdx.x * blockDim.x + threadIdx.x;
    if (d < DD) {
        const float* p = params + (size_t)d * PCOLS;

        float ws[KK], hs[KK], sl[KK + 1];
        float sw = 0.f, sh = 0.f;
#pragma unroll
        for (int j = 0; j < KK; j++) { float v = 1.f / (1.f + expf(-p[j]));      ws[j] = v; sw += v; }
#pragma unroll
        for (int j = 0; j < KK; j++) { float v = 1.f / (1.f + expf(-p[KK + j])); hs[j] = v; sh += v; }
#pragma unroll
        for (int j = 0; j < KK + 1; j++) {
            float v = 1.f / (1.f + expf(-p[2 * KK + j]));
            sl[j] = MIN_SLOPE + v * (MAX_SLOPE - MIN_SLOPE);
        }

        const float rem = (RMAX - RMIN) - KK * MIN_BIN;
        const float fw = rem / sw;
        const float fh = rem / sh;

        float xk = RMIN, yk = RMIN;
#pragma unroll
        for (int j = 0; j < KK; j++) {
            const float wd = MIN_BIN + ws[j] * fw;
            const float ht = MIN_BIN + hs[j] * fh;
            float4 v;
            v.x = yk;
            v.y = ht;
            v.z = 1.f / wd;
            v.w = sl[j];
            g_main[j * DD + d] = v;
            xk += wd;
            yk += ht;
            if (j < 7) g_knots[j * DD + d] = xk;
        }
        g_main[8 * DD + d] = make_float4(0.f, 0.f, 0.f, sl[KK]);
    }
    const int t = blockIdx.x * blockDim.x + threadIdx.x;
    if (t < BB / 2) { ld_out[t] = 0.f; ld_out[t + BB / 2] = 0.f; }
}

#define DT 128   // columns per CTA (== blockDim.x)
#define BT 16    // rows per CTA

__global__ void __launch_bounds__(DT, 10) eval_kernel(const float* __restrict__ x,
                                                      float* __restrict__ y,
                                                      float* __restrict__ ld_out) {
    __shared__ float4 sm4[9 * DT];   // 18.4 KB

    const int tid = threadIdx.x;
    const int lane = tid & 31;
    const int d = blockIdx.x * DT + tid;

    float s0 = 0.f, sK = 0.f;
#pragma unroll
    for (int j = 0; j < 9; j++) {
        const float4 v = g_main[j * DD + d];
        sm4[j * DT + tid] = v;
        if (j == 0) s0 = v.w;
        if (j == 8) sK = v.w;
    }
    const float v1 = g_knots[0 * DD + d];
    const float v2 = g_knots[1 * DD + d];
    const float v3 = g_knots[2 * DD + d];
    const float v4 = g_knots[3 * DD + d];
    const float v5 = g_knots[4 * DD + d];
    const float v6 = g_knots[5 * DD + d];
    const float v7 = g_knots[6 * DD + d];
    __syncthreads();

    const int b0 = blockIdx.y * BT;

    // lane-dependent constants for the transpose reduction
    const bool k4 = (lane & 16) != 0;
    const bool k2 = (lane & 8)  != 0;
    const bool k1 = (lane & 4)  != 0;
    const int  red_row = ((lane >> 4) & 1) * 4 + ((lane >> 3) & 1) * 2 + ((lane >> 2) & 1);

#pragma unroll
    for (int chunk = 0; chunk < BT / 8; chunk++) {
        const float* xp = x + (size_t)(b0 + chunk * 8) * DD + d;
        float*       yp = y + (size_t)(b0 + chunk * 8) * DD + d;

        float v[8];
#pragma unroll
        for (int r = 0; r < 8; r++) {
            const float xv = xp[r * DD];

            // 3-level binary search in registers, carrying the lower knot
            int bin = 0;
            float lo = RMIN;
            if (xv >= v4) { bin = 4; lo = v4; }
            const float c2 = (bin & 4) ? v6 : v2;
            if (xv >= c2) { bin += 2; lo = c2; }
            const float c1 = (bin & 4) ? ((bin & 2) ? v7 : v5)
                                       : ((bin & 2) ? v3 : v1);
            if (xv >= c1) { bin += 1; lo = c1; }

            // one LDS.128 + one immediate-offset LDS.32 (conflict-free)
            const float4* p = &sm4[bin * DT + tid];
            const float4 t = *p;          // {y_k, h, rw, dk}
            const float dk1 = p[DT].w;    // next bin's slope

            const float s   = t.y * t.z;  // h / w
            const float xi  = (xv - lo) * t.z;
            const float xi1 = 1.f - xi;
            const float xx  = xi * xi;
            const float xx1 = xi * xi1;
            const float x11 = xi1 * xi1;

            const float num  = s * xx + t.w * xx1;
            const float den  = fmaf(dk1 + t.w - 2.f * s, xx1, s);
            const float rden = __fdividef(1.f, den);

            float yv = fmaf(t.y * num, rden, t.x);
            const float dnum = s * s * fmaf(dk1, xx, fmaf(2.f * s, xx1, t.w * x11));
            float ldv = __logf(dnum * rden * rden);

            // out-of-range fixup: essentially never taken for N(0,1) data,
            // so pay a branch instead of always-issued predicated ops
            if (__builtin_expect(xv <= RMIN || xv >= RMAX, 0)) {
                if (xv >= RMAX) { yv = fmaf(xv - RMAX, sK, RMAX); ldv = __logf(sK); }
                else            { yv = fmaf(xv - RMIN, s0, RMIN); ldv = __logf(s0); }
            }

            yp[r * DD] = yv;
            v[r] = ldv;
        }

        // Transpose-reduce 8 row-sums across the warp: 9 shuffles total.
        float w4[4];
#pragma unroll
        for (int i = 0; i < 4; i++) {
            const float keep = k4 ? v[i + 4] : v[i];
            const float send = k4 ? v[i] : v[i + 4];
            w4[i] = keep + __shfl_xor_sync(0xffffffffu, send, 16);
        }
        float w2[2];
#pragma unroll
        for (int i = 0; i < 2; i++) {
            const float keep = k2 ? w4[i + 2] : w4[i];
            const float send = k2 ? w4[i] : w4[i + 2];
            w2[i] = keep + __shfl_xor_sync(0xffffffffu, send, 8);
        }
        float z = (k1 ? w2[1] : w2[0]) + __shfl_xor_sync(0xffffffffu, k1 ? w2[0] : w2[1], 4);
        z += __shfl_xor_sync(0xffffffffu, z, 2);
        z += __shfl_xor_sync(0xffffffffu, z, 1);

        if ((lane & 3) == 0) atomicAdd(&ld_out[b0 + chunk * 8 + red_row], z);
    }
}

extern "C" void kernel_launch(void* const* d_in, const int* in_sizes, int n_in,
                              void* d_out, int out_size) {
    const float* x;
    const float* params;
    if (in_sizes[0] == BB * DD) { x = (const float*)d_in[0]; params = (const float*)d_in[1]; }
    else                        { x = (const float*)d_in[1]; params = (const float*)d_in[0]; }

    float* y_out  = (float*)d_out;              // [B, D]
    float* ld_out = y_out + (size_t)BB * DD;    // [B]

    norm_kernel<<<DD / 256, 256>>>(params, ld_out);
    dim3 grid(DD / DT, BB / BT);
    eval_kernel<<<grid, DT>>>(x, y_out, ld_out);
}

// round 5
// speedup vs baseline: 1.3337x; 1.0635x over previous
#include <cuda_runtime.h>
#include <math.h>

#define BB 4096
#define DD 2048
#define KK 8
#define PCOLS 25   // 3K+1

constexpr float RMIN = -5.0f;
constexpr float RMAX = 5.0f;
constexpr float MIN_BIN = 1e-3f;
constexpr float MIN_SLOPE = 1e-3f;
constexpr float MAX_SLOPE = 10.0f;

// Packed main table: [9][DD] of float4 {y_k, h, 1/w, slope_j}; row 8 = {0,0,0,slope_8}.
// dk1 for bin j is row j+1's .w — one immediate-offset LDS.32 from the float4.
__device__ float4 g_main[9 * DD];
// Interior knots x_k[1..7], SoA [7][DD].
__device__ float  g_knots[7 * DD];

__global__ void norm_kernel(const float* __restrict__ params, float* __restrict__ ld_out) {
    const int d = blockIdx.x * blockDim.x + threadIdx.x;
    if (d < DD) {
        const float* p = params + (size_t)d * PCOLS;

        float ws[KK], hs[KK], sl[KK + 1];
        float sw = 0.f, sh = 0.f;
#pragma unroll
        for (int j = 0; j < KK; j++) { float v = 1.f / (1.f + __expf(-p[j]));      ws[j] = v; sw += v; }
#pragma unroll
        for (int j = 0; j < KK; j++) { float v = 1.f / (1.f + __expf(-p[KK + j])); hs[j] = v; sh += v; }
#pragma unroll
        for (int j = 0; j < KK + 1; j++) {
            float v = 1.f / (1.f + __expf(-p[2 * KK + j]));
            sl[j] = MIN_SLOPE + v * (MAX_SLOPE - MIN_SLOPE);
        }

        const float rem = (RMAX - RMIN) - KK * MIN_BIN;
        const float fw = rem / sw;
        const float fh = rem / sh;

        float xk = RMIN, yk = RMIN;
#pragma unroll
        for (int j = 0; j < KK; j++) {
            const float wd = MIN_BIN + ws[j] * fw;
            const float ht = MIN_BIN + hs[j] * fh;
            float4 v;
            v.x = yk;
            v.y = ht;
            v.z = 1.f / wd;
            v.w = sl[j];
            g_main[j * DD + d] = v;
            xk += wd;
            yk += ht;
            if (j < 7) g_knots[j * DD + d] = xk;
        }
        g_main[8 * DD + d] = make_float4(0.f, 0.f, 0.f, sl[KK]);
    }
    const int t = blockIdx.x * blockDim.x + threadIdx.x;
    if (t < BB / 2) { ld_out[t] = 0.f; ld_out[t + BB / 2] = 0.f; }
}

#define DT 256   // columns per CTA (== blockDim.x)
#define BT 32    // rows per CTA

__global__ void __launch_bounds__(DT) eval_kernel(const float* __restrict__ x,
                                                  float* __restrict__ y,
                                                  float* __restrict__ ld_out) {
    __shared__ float4 sm4[9 * DT];   // 36 KB

    const int tid = threadIdx.x;
    const int lane = tid & 31;
    const int d = blockIdx.x * DT + tid;

#pragma unroll
    for (int j = 0; j < 9; j++) sm4[j * DT + tid] = g_main[j * DD + d];

    const float v1 = g_knots[0 * DD + d];
    const float v2 = g_knots[1 * DD + d];
    const float v3 = g_knots[2 * DD + d];
    const float v4 = g_knots[3 * DD + d];
    const float v5 = g_knots[4 * DD + d];
    const float v6 = g_knots[5 * DD + d];
    const float v7 = g_knots[6 * DD + d];
    __syncthreads();

    const int b0 = blockIdx.y * BT;

    // lane-dependent constants for the transpose reduction
    const bool k4 = (lane & 16) != 0;
    const bool k2 = (lane & 8)  != 0;
    const bool k1 = (lane & 4)  != 0;
    const int  red_row = ((lane >> 4) & 1) * 4 + ((lane >> 3) & 1) * 2 + ((lane >> 2) & 1);

#pragma unroll
    for (int chunk = 0; chunk < BT / 8; chunk++) {
        const float* xp = x + (size_t)(b0 + chunk * 8) * DD + d;
        float*       yp = y + (size_t)(b0 + chunk * 8) * DD + d;

        // front-batch the 8 global loads (MLP=8)
        float xin[8];
#pragma unroll
        for (int r = 0; r < 8; r++) xin[r] = __ldg(&xp[r * DD]);

        float v[8];
#pragma unroll
        for (int r = 0; r < 8; r++) {
            const float xv = xin[r];
            // clamp: spline eval at xc is exact at both edges (deriv = s0 / sK)
            const float xc = fminf(fmaxf(xv, RMIN), RMAX);

            // 3-level binary search in registers, carrying the lower knot
            int bin = 0;
            float lo = RMIN;
            if (xc >= v4) { bin = 4; lo = v4; }
            const float c2 = (bin & 4) ? v6 : v2;
            if (xc >= c2) { bin += 2; lo = c2; }
            const float c1 = (bin & 4) ? ((bin & 2) ? v7 : v5)
                                       : ((bin & 2) ? v3 : v1);
            if (xc >= c1) { bin += 1; lo = c1; }

            // one LDS.128 + one immediate-offset LDS.32 (conflict-free)
            const float4* p = &sm4[bin * DT + tid];
            const float4 t = *p;          // {y_k, h, rw, dk}
            const float dk1 = p[DT].w;    // next bin's slope

            const float s   = t.y * t.z;  // h / w
            const float xi  = (xc - lo) * t.z;
            const float xi1 = 1.f - xi;
            const float xx  = xi * xi;
            const float xx1 = xi * xi1;
            const float x11 = xi1 * xi1;

            const float num  = s * xx + t.w * xx1;
            const float den  = fmaf(dk1 + t.w - 2.f * s, xx1, s);
            const float rden = __fdividef(1.f, den);

            float yv = fmaf(t.y * num, rden, t.x);
            const float dnum = s * s * fmaf(dk1, xx, fmaf(2.f * s, xx1, t.w * x11));
            v[r] = __logf(dnum * rden * rden);

            // linear tail extension: (x - xc) is 0 in-range; slope = dk (below) / dk1 (above)
            const float tail = xv - xc;
            yv = fmaf(tail, (tail < 0.f) ? t.w : dk1, yv);

            yp[r * DD] = yv;
        }

        // Transpose-reduce 8 row-sums across the warp: 9 shuffles total.
        float w4[4];
#pragma unroll
        for (int i = 0; i < 4; i++) {
            const float keep = k4 ? v[i + 4] : v[i];
            const float send = k4 ? v[i] : v[i + 4];
            w4[i] = keep + __shfl_xor_sync(0xffffffffu, send, 16);
        }
        float w2[2];
#pragma unroll
        for (int i = 0; i < 2; i++) {
            const float keep = k2 ? w4[i + 2] : w4[i];
            const float send = k2 ? w4[i] : w4[i + 2];
            w2[i] = keep + __shfl_xor_sync(0xffffffffu, send, 8);
        }
        float z = (k1 ? w2[1] : w2[0]) + __shfl_xor_sync(0xffffffffu, k1 ? w2[0] : w2[1], 4);
        z += __shfl_xor_sync(0xffffffffu, z, 2);
        z += __shfl_xor_sync(0xffffffffu, z, 1);

        if ((lane & 3) == 0) atomicAdd(&ld_out[b0 + chunk * 8 + red_row], z);
    }
}

extern "C" void kernel_launch(void* const* d_in, const int* in_sizes, int n_in,
                              void* d_out, int out_size) {
    const float* x;
    const float* params;
    if (in_sizes[0] == BB * DD) { x = (const float*)d_in[0]; params = (const float*)d_in[1]; }
    else                        { x = (const float*)d_in[1]; params = (const float*)d_in[0]; }

    float* y_out  = (float*)d_out;              // [B, D]
    float* ld_out = y_out + (size_t)BB * DD;    // [B]

    norm_kernel<<<DD / 256, 256>>>(params, ld_out);
    dim3 grid(DD / DT, BB / BT);
    eval_kernel<<<grid, DT>>>(x, y_out, ld_out);
}